// round 6
// baseline (speedup 1.0000x reference)
#include <cuda_runtime.h>
#include <math.h>

#define Hh   512
#define Rr   4
#define Ww   32
#define Nn   64
#define Bb   64
#define Tt   256
#define HIDC 759
#define HIDP 768
#define G4C  3036
#define G4E  2048
#define EPSf 1e-6f

// ---- state pool offsets (floats) ----
#define HE0  0
#define HE1  (HE0 + Bb*Hh)
#define CE   (HE1 + Bb*Hh)
#define HC0  (CE  + Bb*Hh)
#define HC1  (HC0 + Bb*HIDP)
#define CC   (HC1 + Bb*HIDP)
#define MO   (CC  + Bb*HIDP)
#define UO   (MO  + Bb*Nn*Ww)
#define PO   (UO  + Bb*Nn)
#define WWO  (PO  + Bb*Nn)
#define LO   (WWO + Bb*Nn)
#define WRO  (LO  + Bb*Nn*Nn)
#define RV0  (WRO + Bb*Rr*Nn)
#define STATE_TOTAL (RV0 + 2*Bb*Rr*Ww)

__device__ float g_state[STATE_TOTAL];
__device__ float g_xproj[(size_t)Bb*Tt*G4E];
__device__ float g_enc  [(size_t)Bb*Tt*Hh];
__device__ float g_eproj[(size_t)Bb*Tt*G4C];
__device__ float g_wrv  [G4C*128];

__device__ __forceinline__ float sigm(float x)  { return 1.f/(1.f+expf(-x)); }
__device__ __forceinline__ float splus(float x) { return x > 0.f ? x + log1pf(expf(-x)) : log1pf(expf(x)); }

__global__ void zero_state() {
    for (int i = blockIdx.x*blockDim.x + threadIdx.x; i < STATE_TOTAL; i += gridDim.x*blockDim.x)
        g_state[i] = 0.f;
}

__global__ void pack_wrv(const float* __restrict__ Wih_c) {
    int e = blockIdx.x*blockDim.x + threadIdx.x;
    if (e < G4C*128) { int m = e >> 7, k = e & 127; g_wrv[e] = Wih_c[m*640 + 512 + k]; }
}

// C[r][m] = bias[m] + sum_{k<512} A[r][k]*W[m][k].  xmode=1: A row r -> x[b=r&63][t=r>>6][:]
__global__ void gemm128(const float* __restrict__ Aext, const float* __restrict__ Wm,
                        const float* __restrict__ bias, int Ncols, int ldw, int xmode, int csel) {
    __shared__ __align__(16) float As[16][132];
    __shared__ __align__(16) float Bs[16][132];
    int tid = threadIdx.x;
    int tx = tid & 15, ty = tid >> 4;
    int row0 = blockIdx.y * 128, col0 = blockIdx.x * 128;
    int ar = tid >> 2, ac = (tid & 3) * 4;
    const float* Ap; long aoff0, aoff1;
    if (xmode) {
        int r0 = row0 + ar, r1 = r0 + 64;
        aoff0 = ((long)(r0 & 63) * Tt + (r0 >> 6)) * Hh;
        aoff1 = ((long)(r1 & 63) * Tt + (r1 >> 6)) * Hh;
        Ap = Aext;
    } else {
        aoff0 = (long)(row0 + ar) * Hh; aoff1 = aoff0 + (long)64 * Hh; Ap = g_enc;
    }
    int brow0 = col0 + ar, brow1 = brow0 + 64;
    bool bv0 = brow0 < Ncols, bv1 = brow1 < Ncols;
    const float* Bp0 = Wm + (long)brow0 * ldw;
    const float* Bp1 = Wm + (long)brow1 * ldw;

    float acc[8][8];
#pragma unroll
    for (int i = 0; i < 8; i++)
#pragma unroll
        for (int j = 0; j < 8; j++) acc[i][j] = 0.f;

    for (int k0 = 0; k0 < 512; k0 += 16) {
        float4 a0 = *(const float4*)(Ap + aoff0 + k0 + ac);
        float4 a1 = *(const float4*)(Ap + aoff1 + k0 + ac);
        float4 b0 = bv0 ? *(const float4*)(Bp0 + k0 + ac) : make_float4(0,0,0,0);
        float4 b1 = bv1 ? *(const float4*)(Bp1 + k0 + ac) : make_float4(0,0,0,0);
        __syncthreads();
        As[ac+0][ar]=a0.x; As[ac+1][ar]=a0.y; As[ac+2][ar]=a0.z; As[ac+3][ar]=a0.w;
        As[ac+0][ar+64]=a1.x; As[ac+1][ar+64]=a1.y; As[ac+2][ar+64]=a1.z; As[ac+3][ar+64]=a1.w;
        Bs[ac+0][ar]=b0.x; Bs[ac+1][ar]=b0.y; Bs[ac+2][ar]=b0.z; Bs[ac+3][ar]=b0.w;
        Bs[ac+0][ar+64]=b1.x; Bs[ac+1][ar+64]=b1.y; Bs[ac+2][ar+64]=b1.z; Bs[ac+3][ar+64]=b1.w;
        __syncthreads();
#pragma unroll
        for (int k = 0; k < 16; k++) {
            float4 fa0 = *(const float4*)&As[k][ty*4];
            float4 fa1 = *(const float4*)&As[k][64 + ty*4];
            float4 fb0 = *(const float4*)&Bs[k][tx*4];
            float4 fb1 = *(const float4*)&Bs[k][64 + tx*4];
            float af[8] = {fa0.x,fa0.y,fa0.z,fa0.w,fa1.x,fa1.y,fa1.z,fa1.w};
            float bf[8] = {fb0.x,fb0.y,fb0.z,fb0.w,fb1.x,fb1.y,fb1.z,fb1.w};
#pragma unroll
            for (int i = 0; i < 8; i++)
#pragma unroll
                for (int j = 0; j < 8; j++) acc[i][j] += af[i]*bf[j];
        }
    }
    float* C = csel ? g_eproj : g_xproj;
#pragma unroll
    for (int i = 0; i < 8; i++) {
        int r = row0 + (i < 4 ? ty*4 + i : 64 + ty*4 + i - 4);
#pragma unroll
        for (int j = 0; j < 8; j++) {
            int cix = col0 + (j < 4 ? tx*4 + j : 64 + tx*4 + j - 4);
            if (cix < Ncols) C[(long)r*Ncols + cix] = acc[i][j] + bias[cix];
        }
    }
}

__device__ __forceinline__ void mm_tile(const float Hs[64][17], const float Ws[4][8][17],
                                        float acc[4][4], int tx, int ty) {
#pragma unroll
    for (int k = 0; k < 16; k++) {
        float w0 = Ws[0][tx][k], w1 = Ws[1][tx][k], w2 = Ws[2][tx][k], w3 = Ws[3][tx][k];
#pragma unroll
        for (int i = 0; i < 4; i++) {
            float hv = Hs[ty*4 + i][k];
            acc[i][0] += hv*w0; acc[i][1] += hv*w1; acc[i][2] += hv*w2; acc[i][3] += hv*w3;
        }
    }
}

// encoder step: fused h@Whh_e^T + LSTM. grid 64 x 128 threads, 8 j-cols per block.
__global__ void enc_step(const float* __restrict__ Whh, int t, int par) {
    __shared__ float Hs[64][17];
    __shared__ float Ws[4][8][17];
    int tid = threadIdx.x, tx = tid & 7, ty = tid >> 3;
    int jb = blockIdx.x * 8;
    const float* h_in  = g_state + HE0 + par * (Bb*Hh);
    float*       h_out = g_state + HE0 + (par^1) * (Bb*Hh);
    const float* xp = g_xproj + (long)t * Bb * G4E;
    float acc[4][4];
#pragma unroll
    for (int i=0;i<4;i++){acc[i][0]=acc[i][1]=acc[i][2]=acc[i][3]=0.f;}

    for (int k0 = 0; k0 < 512; k0 += 16) {
#pragma unroll
        for (int i = 0; i < 8; i++) { int e=i*128+tid; Hs[e>>4][e&15] = h_in[(e>>4)*Hh + k0 + (e&15)]; }
#pragma unroll
        for (int i = 0; i < 4; i++) {
            int e=i*128+tid; int g=e>>7, rem=e&127, j=rem>>4, k=rem&15;
            Ws[g][j][k] = Whh[(g*Hh + jb + j)*Hh + k0 + k];
        }
        __syncthreads();
        mm_tile(Hs, Ws, acc, tx, ty);
        __syncthreads();
    }
    int j = jb + tx;
#pragma unroll
    for (int i = 0; i < 4; i++) {
        int b = ty*4 + i;
        float gi = xp[b*G4E +        j] + acc[i][0];
        float gf = xp[b*G4E +   Hh + j] + acc[i][1];
        float gg = xp[b*G4E + 2*Hh + j] + acc[i][2];
        float go = xp[b*G4E + 3*Hh + j] + acc[i][3];
        float cn = sigm(gf)*g_state[CE + b*Hh + j] + sigm(gi)*tanhf(gg);
        float hn = sigm(go)*tanhf(cn);
        g_state[CE + b*Hh + j] = cn;
        h_out[b*Hh + j] = hn;
        g_enc[((long)t*Bb + b)*Hh + j] = hn;
    }
}

// DNC gates: fused [h|rv]@W^T + LSTM + out write. grid 95 x 128 threads.
__global__ void dnc_gates(const float* __restrict__ Whh_c, int t, int par, float* __restrict__ out) {
    __shared__ float Hs[64][17];
    __shared__ float Ws[4][8][17];
    int tid = threadIdx.x, tx = tid & 7, ty = tid >> 3;
    int jb = blockIdx.x * 8, j = jb + tx;
    const float* h_in  = g_state + HC0 + par * (Bb*HIDP);
    float*       h_out = g_state + HC0 + (par^1) * (Bb*HIDP);
    const float* rv_in = g_state + RV0 + par * (Bb*Rr*Ww);
    const float* ep = g_eproj + (long)t * Bb * G4C;
    float acc[4][4];
#pragma unroll
    for (int i=0;i<4;i++){acc[i][0]=acc[i][1]=acc[i][2]=acc[i][3]=0.f;}

    for (int k0 = 0; k0 < HIDP; k0 += 16) {
#pragma unroll
        for (int i = 0; i < 8; i++) { int e=i*128+tid; Hs[e>>4][e&15] = h_in[(e>>4)*HIDP + k0 + (e&15)]; }
#pragma unroll
        for (int i = 0; i < 4; i++) {
            int e=i*128+tid; int g=e>>7, rem=e&127, jj=rem>>4, k=rem&15;
            int row = jb + jj, kk = k0 + k;
            Ws[g][jj][k] = (row < HIDC && kk < HIDC) ? Whh_c[(long)(g*HIDC + row)*HIDC + kk] : 0.f;
        }
        __syncthreads();
        mm_tile(Hs, Ws, acc, tx, ty);
        __syncthreads();
    }
    for (int k0 = 0; k0 < 128; k0 += 16) {
#pragma unroll
        for (int i = 0; i < 8; i++) { int e=i*128+tid; Hs[e>>4][e&15] = rv_in[(e>>4)*128 + k0 + (e&15)]; }
#pragma unroll
        for (int i = 0; i < 4; i++) {
            int e=i*128+tid; int g=e>>7, rem=e&127, jj=rem>>4, k=rem&15;
            int row = jb + jj;
            Ws[g][jj][k] = (row < HIDC) ? g_wrv[(g*HIDC + row)*128 + k0 + k] : 0.f;
        }
        __syncthreads();
        mm_tile(Hs, Ws, acc, tx, ty);
        __syncthreads();
    }
    if (j < HIDC) {
#pragma unroll
        for (int i = 0; i < 4; i++) {
            int b = ty*4 + i;
            float gi = ep[b*G4C +          j] + acc[i][0];
            float gf = ep[b*G4C +   HIDC + j] + acc[i][1];
            float gg = ep[b*G4C + 2*HIDC + j] + acc[i][2];
            float go = ep[b*G4C + 3*HIDC + j] + acc[i][3];
            float cn = sigm(gf)*g_state[CC + b*HIDP + j] + sigm(gi)*tanhf(gg);
            float hn = sigm(go)*tanhf(cn);
            g_state[CC + b*HIDP + j] = cn;
            h_out[b*HIDP + j] = hn;
            if (j < Hh) out[((long)b*Tt + t)*Hh + j] = hn;
        }
    }
}

// DNC memory machinery: one block per batch element, 256 threads.
__global__ void dnc_mem(int par) {
    int b = blockIdx.x, tid = threadIdx.x;
    int np = par ^ 1;
    const float* h_new = g_state + HC0 + np*(Bb*HIDP) + b*HIDP;

    __shared__ float rk[4][32], wk[32], er[32], wv[32];
    __shared__ float rs[4], fg[4], rm[4][3], rmraw[12];
    __shared__ float wstr, ag, wg, wkn, swsum, rkn[4];
    __shared__ float u_s[64], p_s[64], ww_o[64], ww_n[64], su[64], asort[64], cw[64], sim[64], mnorm[64];
    __shared__ int   rank_s[64];
    __shared__ float wr_o[4][64], wr_n[4][64], cr_s[4][64], fw_s[4][64], bw_s[4][64];
    __shared__ float Ms[64][33];
    __shared__ float Ls[64][65];
    __shared__ float red[2];

    // P0: interface + state load
    if (tid < 247) {
        float v = h_new[512 + tid];
        if      (tid < 128) rk[tid>>5][tid&31] = tanhf(v);
        else if (tid < 132) rs[tid-128] = splus(v);
        else if (tid < 164) wk[tid-132] = tanhf(v);
        else if (tid ==164) wstr = splus(v);
        else if (tid < 197) er[tid-165] = sigm(v);
        else if (tid < 229) wv[tid-197] = tanhf(v);
        else if (tid < 233) fg[tid-229] = sigm(v);
        else if (tid ==233) ag = sigm(v);
        else if (tid ==234) wg = sigm(v);
        else                rmraw[tid-235] = v;
    }
    if (tid < 64) {
        u_s[tid]  = g_state[UO  + b*64 + tid];
        p_s[tid]  = g_state[PO  + b*64 + tid];
        ww_o[tid] = g_state[WWO + b*64 + tid];
    }
    wr_o[tid>>6][tid&63] = g_state[WRO + b*256 + tid];
#pragma unroll
    for (int i = 0; i < 8; i++)  { int e=i*256+tid; Ms[e>>5][e&31] = g_state[MO + b*2048 + e]; }
#pragma unroll
    for (int i = 0; i < 16; i++) { int e=i*256+tid; Ls[e>>6][e&63] = g_state[LO + b*4096 + e]; }
    __syncthreads();

    // P1: rm softmax, key norms, usage update
    if (tid < 4) {
        float x0=rmraw[tid*3], x1=rmraw[tid*3+1], x2=rmraw[tid*3+2];
        float m = fmaxf(x0, fmaxf(x1, x2));
        float e0=expf(x0-m), e1=expf(x1-m), e2=expf(x2-m), s=e0+e1+e2;
        rm[tid][0]=e0/s; rm[tid][1]=e1/s; rm[tid][2]=e2/s;
    } else if (tid == 4) {
        float s = EPSf;
        for (int w = 0; w < 32; w++) s += wk[w]*wk[w];
        wkn = rsqrtf(s);
    } else if (tid >= 8 && tid < 12) {
        int r = tid - 8; float s = EPSf;
        for (int w = 0; w < 32; w++) s += rk[r][w]*rk[r][w];
        rkn[r] = rsqrtf(s);
    } else if (tid >= 64 && tid < 128) {
        int n = tid - 64;
        float psi = 1.f;
#pragma unroll
        for (int r = 0; r < 4; r++) psi *= 1.f - fg[r]*wr_o[r][n];
        float uo = u_s[n], w = ww_o[n];
        u_s[n] = (uo + w - uo*w) * psi;
    }
    __syncthreads();

    // P2: stable rank + scatter sorted u; write-content sim (old M)
    if (tid < 64) {
        float un = u_s[tid]; int rnk = 0;
        for (int m = 0; m < 64; m++) {
            float um = u_s[m];
            rnk += (um < un) || (um == un && m < tid);
        }
        rank_s[tid] = rnk;
        su[rnk] = un;
    } else if (tid < 128) {
        int n = tid - 64; float ss = EPSf, d = 0.f;
        for (int w = 0; w < 32; w++) { float m = Ms[n][w]; ss += m*m; d += wk[w]*m; }
        sim[n] = d * rsqrtf(ss) * wkn;
    }
    __syncthreads();

    // P3: cumprod allocation + softmax max
    if (tid == 0) {
        float cp = 1.f;
        for (int i = 0; i < 64; i++) { asort[i] = (1.f - su[i]) * cp; cp *= su[i]; }
        float mx = -1e30f;
        for (int n = 0; n < 64; n++) mx = fmaxf(mx, sim[n]*wstr);
        red[0] = mx;
    }
    __syncthreads();
    if (tid < 64) cw[tid] = expf(sim[tid]*wstr - red[0]);
    __syncthreads();
    if (tid == 0) { float s = 0.f; for (int n = 0; n < 64; n++) s += cw[n]; red[1] = s; }
    __syncthreads();
    if (tid < 64) {
        float c = cw[tid] / red[1];
        float a = asort[rank_s[tid]];
        ww_n[tid] = wg * (ag*a + (1.f-ag)*c);
    }
    __syncthreads();

    // P4: swsum; M update; L update (old p)
    if (tid == 0) { float s = 0.f; for (int n = 0; n < 64; n++) s += ww_n[n]; swsum = s; }
#pragma unroll
    for (int i = 0; i < 8; i++) {
        int e = i*256 + tid, n = e>>5, w = e&31;
        Ms[n][w] = Ms[n][w]*(1.f - ww_n[n]*er[w]) + ww_n[n]*wv[w];
    }
#pragma unroll
    for (int i = 0; i < 16; i++) {
        int e = i*256 + tid, ii = e>>6, jj = e&63;
        Ls[ii][jj] = (ii == jj) ? 0.f
                   : (1.f - ww_n[ii] - ww_n[jj])*Ls[ii][jj] + ww_n[ii]*p_s[jj];
    }
    __syncthreads();

    // P5: p update; new-M norms
    if (tid < 64) {
        p_s[tid] = (1.f - swsum)*p_s[tid] + ww_n[tid];
        float ss = EPSf;
        for (int w = 0; w < 32; w++) ss += Ms[tid][w]*Ms[tid][w];
        mnorm[tid] = rsqrtf(ss);
    }
    __syncthreads();

    // P6: read-content logits (new M); fw/bw (new L, old wr)
    {
        int r = tid >> 6, n = tid & 63;
        float d = 0.f;
        for (int w = 0; w < 32; w++) d += rk[r][w]*Ms[n][w];
        cr_s[r][n] = d * mnorm[n] * rkn[r] * rs[r];
        float f = 0.f, bb = 0.f;
        for (int m = 0; m < 64; m++) {
            float wrm = wr_o[r][m];
            f  += Ls[n][m]*wrm;
            bb += Ls[m][n]*wrm;
        }
        fw_s[r][n] = f; bw_s[r][n] = bb;
    }
    __syncthreads();

    // P7: per-head softmax of read-content logits
    if (tid < 4) {
        int r = tid; float mx = -1e30f;
        for (int n = 0; n < 64; n++) mx = fmaxf(mx, cr_s[r][n]);
        float s = 0.f;
        for (int n = 0; n < 64; n++) { float e = expf(cr_s[r][n]-mx); cr_s[r][n] = e; s += e; }
        float inv = 1.f/s;
        for (int n = 0; n < 64; n++) cr_s[r][n] *= inv;
    }
    __syncthreads();

    // P8: new read weights
    {
        int r = tid >> 6, n = tid & 63;
        wr_n[r][n] = rm[r][0]*bw_s[r][n] + rm[r][1]*cr_s[r][n] + rm[r][2]*fw_s[r][n];
    }
    __syncthreads();

    // P9: read vectors + state write-back
    if (tid < 128) {
        int r = tid >> 5, w = tid & 31;
        float s = 0.f;
        for (int n = 0; n < 64; n++) s += wr_n[r][n]*Ms[n][w];
        g_state[RV0 + np*(Bb*128) + b*128 + tid] = s;
    }
    if (tid < 64) {
        g_state[UO  + b*64 + tid] = u_s[tid];
        g_state[PO  + b*64 + tid] = p_s[tid];
        g_state[WWO + b*64 + tid] = ww_n[tid];
    }
    g_state[WRO + b*256 + tid] = wr_n[tid>>6][tid&63];
#pragma unroll
    for (int i = 0; i < 8; i++)  { int e=i*256+tid; g_state[MO + b*2048 + e] = Ms[e>>5][e&31]; }
#pragma unroll
    for (int i = 0; i < 16; i++) { int e=i*256+tid; g_state[LO + b*4096 + e] = Ls[e>>6][e&63]; }
}

extern "C" void kernel_launch(void* const* d_in, const int* in_sizes, int n_in,
                              void* d_out, int out_size) {
    const float* x     = (const float*)d_in[0];
    const float* Wih_e = (const float*)d_in[1];
    const float* Whh_e = (const float*)d_in[2];
    const float* b_e   = (const float*)d_in[3];
    const float* Wih_c = (const float*)d_in[4];
    const float* Whh_c = (const float*)d_in[5];
    const float* b_c   = (const float*)d_in[6];
    float* out = (float*)d_out;

    zero_state<<<256, 256>>>();
    pack_wrv<<<(G4C*128 + 255)/256, 256>>>(Wih_c);

    // x @ Wih_e^T + b_e  -> g_xproj [t][b][2048]
    gemm128<<<dim3(16, 128), 256>>>(x, Wih_e, b_e, G4E, 512, 1, 0);

    for (int t = 0; t < Tt; t++)
        enc_step<<<64, 128>>>(Whh_e, t, t & 1);

    // enc @ Wih_c[:, :512]^T + b_c -> g_eproj [t][b][3036]
    gemm128<<<dim3(24, 128), 256>>>(nullptr, Wih_c, b_c, G4C, 640, 0, 1);

    for (int t = 0; t < Tt; t++) {
        dnc_gates<<<95, 128>>>(Whh_c, t, t & 1, out);
        dnc_mem<<<64, 256>>>(t & 1);
    }
}

// round 7
// speedup vs baseline: 1.5761x; 1.5761x over previous
#include <cuda_runtime.h>
#include <math.h>

#define Hh   512
#define Rr   4
#define Ww   32
#define Nn   64
#define Bb   64
#define Tt   256
#define HIDC 759
#define KCOMB 896          // 759 h + 128 rv + 9 pad
#define G4C  3036
#define G4E  2048
#define EPSf 1e-6f

#define NBLK 128

// ---- global buffers ----
__device__ float g_hTe [2][Hh*Bb];                    // encoder h, transposed [k][b]
__device__ float g_comb[2][KCOMB*Bb];                 // DNC [h(759) | rv(128) | pad] x [b]
__device__ float g_xprojT[(size_t)Tt*G4E*Bb];         // [t][col][b]
__device__ float g_eprojT[(size_t)Tt*G4C*Bb];         // [t][col][b]
__device__ float g_encT  [(size_t)Tt*Hh*Bb];          // [t][j][b]

__device__ unsigned g_cnt = 0u, g_gen = 0u;

__device__ __forceinline__ float sigm(float x)  { return 1.f/(1.f+expf(-x)); }
__device__ __forceinline__ float splus(float x) { return x > 0.f ? x + log1pf(expf(-x)) : log1pf(expf(x)); }

__device__ __forceinline__ void grid_sync() {
    __threadfence();
    __syncthreads();
    if (threadIdx.x == 0) {
        volatile unsigned* vgen = &g_gen;
        unsigned g = *vgen;
        if (atomicAdd(&g_cnt, 1u) == (unsigned)(NBLK - 1)) {
            *((volatile unsigned*)&g_cnt) = 0u;
            __threadfence();
            *vgen = g + 1u;
        } else {
            while (*vgen == g) { __nanosleep(64); }
        }
    }
    __syncthreads();
}

__global__ void zero_bufs() {
    int n1 = 2*Hh*Bb, n2 = 2*KCOMB*Bb;
    for (int i = blockIdx.x*blockDim.x + threadIdx.x; i < n1; i += gridDim.x*blockDim.x)
        ((float*)g_hTe)[i] = 0.f;
    for (int i = blockIdx.x*blockDim.x + threadIdx.x; i < n2; i += gridDim.x*blockDim.x)
        ((float*)g_comb)[i] = 0.f;
}

// ============ big GEMM:  proj[t][col][b] = bias[col] + sum_k A[(t,b)][k] * W[col][k] ============
// xmode=1: A row r=(t*64+b) -> x[b][t][k].  xmode=0: A from g_encT[t][k][b].
__global__ void gemm128(const float* __restrict__ x, const float* __restrict__ Wm,
                        const float* __restrict__ bias, float* __restrict__ proj,
                        int Ncols, int ldw, int xmode) {
    __shared__ __align__(16) float As[16][132];
    __shared__ __align__(16) float Bs[16][132];
    int tid = threadIdx.x;
    int tx = tid & 15, ty = tid >> 4;
    int row0 = blockIdx.y * 128, col0 = blockIdx.x * 128;
    int ar = tid >> 2, ac = (tid & 3) * 4;

    long aoff0 = 0, aoff1 = 0;
    if (xmode) {
        int r0 = row0 + ar, r1 = r0 + 64;
        aoff0 = ((long)(r0 & 63) * Tt + (r0 >> 6)) * Hh;
        aoff1 = ((long)(r1 & 63) * Tt + (r1 >> 6)) * Hh;
    }
    int brow0 = col0 + ar, brow1 = brow0 + 64;
    bool bv0 = brow0 < Ncols, bv1 = brow1 < Ncols;
    const float* Bp0 = Wm + (long)brow0 * ldw;
    const float* Bp1 = Wm + (long)brow1 * ldw;

    float acc[8][8];
#pragma unroll
    for (int i = 0; i < 8; i++)
#pragma unroll
        for (int j = 0; j < 8; j++) acc[i][j] = 0.f;

    for (int k0 = 0; k0 < 512; k0 += 16) {
        float4 b0 = bv0 ? *(const float4*)(Bp0 + k0 + ac) : make_float4(0,0,0,0);
        float4 b1 = bv1 ? *(const float4*)(Bp1 + k0 + ac) : make_float4(0,0,0,0);
        if (xmode) {
            float4 a0 = *(const float4*)(x + aoff0 + k0 + ac);
            float4 a1 = *(const float4*)(x + aoff1 + k0 + ac);
            __syncthreads();
            As[ac+0][ar]=a0.x; As[ac+1][ar]=a0.y; As[ac+2][ar]=a0.z; As[ac+3][ar]=a0.w;
            As[ac+0][ar+64]=a1.x; As[ac+1][ar+64]=a1.y; As[ac+2][ar+64]=a1.z; As[ac+3][ar+64]=a1.w;
        } else {
            __syncthreads();
#pragma unroll
            for (int i = 0; i < 8; i++) {
                int e = i*256 + tid; int k = e >> 7, rr = e & 127;
                int r = row0 + rr;
                As[k][rr] = g_encT[(((size_t)(r >> 6))*Hh + k0 + k)*Bb + (r & 63)];
            }
        }
        Bs[ac+0][ar]=b0.x; Bs[ac+1][ar]=b0.y; Bs[ac+2][ar]=b0.z; Bs[ac+3][ar]=b0.w;
        Bs[ac+0][ar+64]=b1.x; Bs[ac+1][ar+64]=b1.y; Bs[ac+2][ar+64]=b1.z; Bs[ac+3][ar+64]=b1.w;
        __syncthreads();
#pragma unroll
        for (int k = 0; k < 16; k++) {
            float4 fa0 = *(const float4*)&As[k][ty*4];
            float4 fa1 = *(const float4*)&As[k][64 + ty*4];
            float4 fb0 = *(const float4*)&Bs[k][tx*4];
            float4 fb1 = *(const float4*)&Bs[k][64 + tx*4];
            float af[8] = {fa0.x,fa0.y,fa0.z,fa0.w,fa1.x,fa1.y,fa1.z,fa1.w};
            float bf[8] = {fb0.x,fb0.y,fb0.z,fb0.w,fb1.x,fb1.y,fb1.z,fb1.w};
#pragma unroll
            for (int i = 0; i < 8; i++)
#pragma unroll
                for (int j = 0; j < 8; j++) acc[i][j] += af[i]*bf[j];
        }
    }
#pragma unroll
    for (int i = 0; i < 8; i++) {
        int r = row0 + (i < 4 ? ty*4 + i : 64 + ty*4 + i - 4);
        int t = r >> 6, b = r & 63;
#pragma unroll
        for (int j = 0; j < 8; j++) {
            int cix = col0 + (j < 4 ? tx*4 + j : 64 + tx*4 + j - 4);
            if (cix < Ncols)
                proj[((size_t)t*Ncols + cix)*Bb + b] = acc[i][j] + bias[cix];
        }
    }
}

// ============ persistent encoder: 128 blocks x 256 threads, 4 j per block ============
__global__ void __launch_bounds__(256, 1) enc_persist(const float* __restrict__ Whh) {
    extern __shared__ __align__(16) float sm[];
    float* Wc = sm;              // 4j*4g*512 = 8192
    float* Hs = sm + 8192;       // 128*64

    int tid = threadIdx.x, bid = blockIdx.x;
    int jb = bid * 4;
    int jl = tid >> 6, b = tid & 63;
    int j = jb + jl;

    // cache weights
#pragma unroll
    for (int i = 0; i < 8; i++) {
        int q = i*256 + tid;           // float4 index, 2048 total
        int row = q >> 7, k4 = q & 127;
        int wjl = row >> 2, g = row & 3;
        ((float4*)(Wc + (wjl*4+g)*512))[k4] =
            ((const float4*)(Whh + ((size_t)(g*Hh + jb + wjl))*Hh))[k4];
    }
    float c = 0.f;
    const float* wb = Wc + jl*4*512;

    for (int t = 0; t < Tt; t++) {
        int par = t & 1;
        const float* hin = g_hTe[par];
        float a0 = 0.f, a1 = 0.f, a2 = 0.f, a3 = 0.f;
        for (int k0 = 0; k0 < 512; k0 += 128) {
            __syncthreads();
            const float4* src = (const float4*)(hin + (size_t)k0*Bb);
#pragma unroll
            for (int i = 0; i < 8; i++) {
                int q = i*256 + tid;
                ((float4*)Hs)[q] = __ldcg(src + q);
            }
            __syncthreads();
#pragma unroll 4
            for (int kk = 0; kk < 128; kk += 4) {
                float4 wi = *(const float4*)(wb + 0*512 + k0 + kk);
                float4 wf = *(const float4*)(wb + 1*512 + k0 + kk);
                float4 wg = *(const float4*)(wb + 2*512 + k0 + kk);
                float4 wo = *(const float4*)(wb + 3*512 + k0 + kk);
                float h0 = Hs[(kk+0)*64 + b], h1 = Hs[(kk+1)*64 + b];
                float h2 = Hs[(kk+2)*64 + b], h3 = Hs[(kk+3)*64 + b];
                a0 = fmaf(wi.x,h0,a0); a0 = fmaf(wi.y,h1,a0); a0 = fmaf(wi.z,h2,a0); a0 = fmaf(wi.w,h3,a0);
                a1 = fmaf(wf.x,h0,a1); a1 = fmaf(wf.y,h1,a1); a1 = fmaf(wf.z,h2,a1); a1 = fmaf(wf.w,h3,a1);
                a2 = fmaf(wg.x,h0,a2); a2 = fmaf(wg.y,h1,a2); a2 = fmaf(wg.z,h2,a2); a2 = fmaf(wg.w,h3,a2);
                a3 = fmaf(wo.x,h0,a3); a3 = fmaf(wo.y,h1,a3); a3 = fmaf(wo.z,h2,a3); a3 = fmaf(wo.w,h3,a3);
            }
        }
        const float* xp = g_xprojT + (size_t)t*G4E*Bb;
        float gi = xp[(0*Hh + j)*Bb + b] + a0;
        float gf = xp[(1*Hh + j)*Bb + b] + a1;
        float gg = xp[(2*Hh + j)*Bb + b] + a2;
        float go = xp[(3*Hh + j)*Bb + b] + a3;
        c = sigm(gf)*c + sigm(gi)*tanhf(gg);
        float hn = sigm(go)*tanhf(c);
        g_hTe[par^1][j*Bb + b] = hn;
        g_encT[((size_t)t*Hh + j)*Bb + b] = hn;
        grid_sync();
    }
}

// ============ persistent DNC: 128 blocks x 384 threads, 6 j per block ============
#define WC_F   (24*KCOMB)           // 21504
#define HS_F   (128*64)             // 8192
#define MEM_F  8512

__global__ void __launch_bounds__(384, 1) dnc_persist(const float* __restrict__ Whh_c,
                                                      const float* __restrict__ Wih_c,
                                                      float* __restrict__ out) {
    extern __shared__ __align__(16) float sm[];
    float* Wc  = sm;
    float* Hs  = sm + WC_F;
    float* MEM = sm + WC_F + HS_F;

    // machinery pool carve
    float* Ms   = MEM;               // 64x33
    float* Ls   = MEM + 2112;        // 64x65
    float* u_s  = MEM + 6272;
    float* p_s  = u_s + 64;
    float* wwo  = p_s + 64;
    float* wwn  = wwo + 64;
    float* su   = wwn + 64;
    float* asrt = su + 64;
    float* cwv  = asrt + 64;
    float* simv = cwv + 64;
    float* mno  = simv + 64;
    int*   rnk  = (int*)(mno + 64);
    float* wro  = mno + 128;         // 4x64
    float* wrn  = wro + 256;
    float* crs  = wrn + 256;
    float* fws  = crs + 256;
    float* bws  = fws + 256;
    float* rk   = bws + 256;         // 4x32
    float* wk   = rk + 128;
    float* er   = wk + 32;
    float* wv   = er + 32;
    float* rs   = wv + 32;           // 4
    float* fg   = rs + 4;
    float* rmm  = fg + 4;            // 12
    float* rmraw= rmm + 12;          // 12
    float* scal = rmraw + 12;        // 11

    int tid = threadIdx.x, bid = blockIdx.x;
    int jb = bid * 6;
    int jl = tid >> 6, b = tid & 63;
    int j = jb + jl;
    bool jv = j < HIDC;

    // cache weights [row=jl*4+g][k<896]
    for (int i = 0; i < 56; i++) {
        int idx = i*384 + tid;
        if (idx < WC_F) {
            int row = idx / KCOMB, k = idx - row*KCOMB;
            int wjl = row >> 2, g = row & 3;
            int wj = jb + wjl;
            float v = 0.f;
            if (wj < HIDC) {
                if (k < HIDC)        v = Whh_c[((size_t)(g*HIDC + wj))*HIDC + k];
                else if (k < HIDC+128) v = Wih_c[((size_t)(g*HIDC + wj))*640 + 512 + (k - HIDC)];
            }
            Wc[idx] = v;
        }
    }
    if (bid < 64) {
        for (int idx = tid; idx < MEM_F; idx += 384) MEM[idx] = 0.f;
    }
    float c = 0.f;
    const float* wbp = Wc + jl*4*KCOMB;

    for (int t = 0; t < Tt; t++) {
        int par = t & 1;
        const float* combP = g_comb[par];
        float* combN = g_comb[par^1];

        float a0 = 0.f, a1 = 0.f, a2 = 0.f, a3 = 0.f;
        for (int k0 = 0; k0 < KCOMB; k0 += 128) {
            __syncthreads();
            const float4* src = (const float4*)(combP + (size_t)k0*Bb);
#pragma unroll
            for (int i = 0; i < 6; i++) {
                int q = i*384 + tid;
                if (q < 2048) ((float4*)Hs)[q] = __ldcg(src + q);
            }
            __syncthreads();
#pragma unroll 4
            for (int kk = 0; kk < 128; kk += 4) {
                float4 wi = *(const float4*)(wbp + 0*KCOMB + k0 + kk);
                float4 wf = *(const float4*)(wbp + 1*KCOMB + k0 + kk);
                float4 wg = *(const float4*)(wbp + 2*KCOMB + k0 + kk);
                float4 wo = *(const float4*)(wbp + 3*KCOMB + k0 + kk);
                float h0 = Hs[(kk+0)*64 + b], h1 = Hs[(kk+1)*64 + b];
                float h2 = Hs[(kk+2)*64 + b], h3 = Hs[(kk+3)*64 + b];
                a0 = fmaf(wi.x,h0,a0); a0 = fmaf(wi.y,h1,a0); a0 = fmaf(wi.z,h2,a0); a0 = fmaf(wi.w,h3,a0);
                a1 = fmaf(wf.x,h0,a1); a1 = fmaf(wf.y,h1,a1); a1 = fmaf(wf.z,h2,a1); a1 = fmaf(wf.w,h3,a1);
                a2 = fmaf(wg.x,h0,a2); a2 = fmaf(wg.y,h1,a2); a2 = fmaf(wg.z,h2,a2); a2 = fmaf(wg.w,h3,a2);
                a3 = fmaf(wo.x,h0,a3); a3 = fmaf(wo.y,h1,a3); a3 = fmaf(wo.z,h2,a3); a3 = fmaf(wo.w,h3,a3);
            }
        }
        if (jv) {
            const float* ep = g_eprojT + (size_t)t*G4C*Bb;
            float gi = ep[((size_t)(0*HIDC + j))*Bb + b] + a0;
            float gf = ep[((size_t)(1*HIDC + j))*Bb + b] + a1;
            float gg = ep[((size_t)(2*HIDC + j))*Bb + b] + a2;
            float go = ep[((size_t)(3*HIDC + j))*Bb + b] + a3;
            c = sigm(gf)*c + sigm(gi)*tanhf(gg);
            float hn = sigm(go)*tanhf(c);
            combN[j*Bb + b] = hn;
            if (j < Hh) out[((size_t)b*Tt + t)*Hh + j] = hn;
        }
        grid_sync();

        // ---------------- memory machinery (blocks 0..63, batch = bid) ----------------
        if (bid < 64) {
            int mb = bid;
            // P0: interface
            if (tid < 247) {
                float v = __ldcg(&combN[(Hh + tid)*Bb + mb]);
                if      (tid < 128) rk[tid] = tanhf(v);
                else if (tid < 132) rs[tid-128] = splus(v);
                else if (tid < 164) wk[tid-132] = tanhf(v);
                else if (tid ==164) scal[0] = splus(v);
                else if (tid < 197) er[tid-165] = sigm(v);
                else if (tid < 229) wv[tid-197] = tanhf(v);
                else if (tid < 233) fg[tid-229] = sigm(v);
                else if (tid ==233) scal[1] = sigm(v);
                else if (tid ==234) scal[2] = sigm(v);
                else                rmraw[tid-235] = v;
            }
            __syncthreads();
            // P1
            if (tid < 4) {
                float x0=rmraw[tid*3], x1=rmraw[tid*3+1], x2=rmraw[tid*3+2];
                float m = fmaxf(x0, fmaxf(x1, x2));
                float e0=expf(x0-m), e1=expf(x1-m), e2=expf(x2-m), s=e0+e1+e2;
                rmm[tid*3]=e0/s; rmm[tid*3+1]=e1/s; rmm[tid*3+2]=e2/s;
            } else if (tid == 4) {
                float s = EPSf;
                for (int w = 0; w < 32; w++) s += wk[w]*wk[w];
                scal[3] = rsqrtf(s);
            } else if (tid >= 8 && tid < 12) {
                int r = tid - 8; float s = EPSf;
                for (int w = 0; w < 32; w++) s += rk[r*32+w]*rk[r*32+w];
                scal[5+r] = rsqrtf(s);
            } else if (tid >= 64 && tid < 128) {
                int n = tid - 64;
                float psi = 1.f;
#pragma unroll
                for (int r = 0; r < 4; r++) psi *= 1.f - fg[r]*wro[r*64+n];
                float uo = u_s[n], w = wwo[n];
                u_s[n] = (uo + w - uo*w) * psi;
            }
            __syncthreads();
            // P2: stable rank + sorted scatter; write-content sim (old M)
            if (tid < 64) {
                float un = u_s[tid]; int r = 0;
                for (int m = 0; m < 64; m++) {
                    float um = u_s[m];
                    r += (um < un) || (um == un && m < tid);
                }
                rnk[tid] = r;
                su[r] = un;
            } else if (tid < 128) {
                int n = tid - 64; float ss = EPSf, d = 0.f;
                for (int w = 0; w < 32; w++) { float m = Ms[n*33+w]; ss += m*m; d += wk[w]*m; }
                simv[n] = d * rsqrtf(ss) * scal[3];
            }
            __syncthreads();
            // P3
            if (tid == 0) {
                float cp = 1.f;
                for (int i = 0; i < 64; i++) { asrt[i] = (1.f - su[i]) * cp; cp *= su[i]; }
                float mx = -1e30f;
                for (int n = 0; n < 64; n++) mx = fmaxf(mx, simv[n]*scal[0]);
                scal[9] = mx;
            }
            __syncthreads();
            if (tid < 64) cwv[tid] = expf(simv[tid]*scal[0] - scal[9]);
            __syncthreads();
            if (tid == 0) { float s = 0.f; for (int n = 0; n < 64; n++) s += cwv[n]; scal[10] = s; }
            __syncthreads();
            if (tid < 64) {
                float cc = cwv[tid] / scal[10];
                float a  = asrt[rnk[tid]];
                wwn[tid] = scal[2] * (scal[1]*a + (1.f-scal[1])*cc);
            }
            __syncthreads();
            // P4
            if (tid == 0) { float s = 0.f; for (int n = 0; n < 64; n++) s += wwn[n]; scal[4] = s; }
            if (tid < 256) {
#pragma unroll
                for (int i = 0; i < 8; i++) {
                    int e = i*256 + tid, n = e>>5, w = e&31;
                    Ms[n*33+w] = Ms[n*33+w]*(1.f - wwn[n]*er[w]) + wwn[n]*wv[w];
                }
#pragma unroll
                for (int i = 0; i < 16; i++) {
                    int e = i*256 + tid, ii = e>>6, jj = e&63;
                    Ls[ii*65+jj] = (ii == jj) ? 0.f
                               : (1.f - wwn[ii] - wwn[jj])*Ls[ii*65+jj] + wwn[ii]*p_s[jj];
                }
            }
            __syncthreads();
            // P5
            if (tid < 64) {
                p_s[tid] = (1.f - scal[4])*p_s[tid] + wwn[tid];
                float ss = EPSf;
                for (int w = 0; w < 32; w++) ss += Ms[tid*33+w]*Ms[tid*33+w];
                mno[tid] = rsqrtf(ss);
            }
            __syncthreads();
            // P6
            if (tid < 256) {
                int r = tid >> 6, n = tid & 63;
                float d = 0.f;
                for (int w = 0; w < 32; w++) d += rk[r*32+w]*Ms[n*33+w];
                crs[r*64+n] = d * mno[n] * scal[5+r] * rs[r];
                float f = 0.f, bb2 = 0.f;
                for (int m = 0; m < 64; m++) {
                    float wrm = wro[r*64+m];
                    f   += Ls[n*65+m]*wrm;
                    bb2 += Ls[m*65+n]*wrm;
                }
                fws[r*64+n] = f; bws[r*64+n] = bb2;
            }
            __syncthreads();
            // P7
            if (tid < 4) {
                int r = tid; float mx = -1e30f;
                for (int n = 0; n < 64; n++) mx = fmaxf(mx, crs[r*64+n]);
                float s = 0.f;
                for (int n = 0; n < 64; n++) { float e = expf(crs[r*64+n]-mx); crs[r*64+n] = e; s += e; }
                float inv = 1.f/s;
                for (int n = 0; n < 64; n++) crs[r*64+n] *= inv;
            }
            __syncthreads();
            // P8
            if (tid < 256) {
                int r = tid >> 6, n = tid & 63;
                wrn[r*64+n] = rmm[r*3+0]*bws[r*64+n] + rmm[r*3+1]*crs[r*64+n] + rmm[r*3+2]*fws[r*64+n];
            }
            __syncthreads();
            // P9: rv + state rotate
            if (tid < 128) {
                int r = tid >> 5, w = tid & 31;
                float s = 0.f;
                for (int n = 0; n < 64; n++) s += wrn[r*64+n]*Ms[n*33+w];
                combN[(HIDC + tid)*Bb + mb] = s;
            }
            if (tid < 64) wwo[tid] = wwn[tid];
            if (tid < 256) wro[tid] = wrn[tid];
            __syncthreads();
        }
        grid_sync();
    }
}

extern "C" void kernel_launch(void* const* d_in, const int* in_sizes, int n_in,
                              void* d_out, int out_size) {
    const float* x     = (const float*)d_in[0];
    const float* Wih_e = (const float*)d_in[1];
    const float* Whh_e = (const float*)d_in[2];
    const float* b_e   = (const float*)d_in[3];
    const float* Wih_c = (const float*)d_in[4];
    const float* Whh_c = (const float*)d_in[5];
    const float* b_c   = (const float*)d_in[6];
    float* out = (float*)d_out;

    static int attrs_set = 0;
    if (!attrs_set) {
        cudaFuncSetAttribute(enc_persist, cudaFuncAttributeMaxDynamicSharedMemorySize, 65536);
        cudaFuncSetAttribute(dnc_persist, cudaFuncAttributeMaxDynamicSharedMemorySize,
                             (WC_F + HS_F + MEM_F) * 4);
        attrs_set = 1;
    }

    float* xprojT; cudaGetSymbolAddress((void**)&xprojT, g_xprojT);
    float* eprojT; cudaGetSymbolAddress((void**)&eprojT, g_eprojT);

    zero_bufs<<<64, 256>>>();

    // x @ Wih_e^T + b_e  -> g_xprojT
    gemm128<<<dim3(16, 128), 256>>>(x, Wih_e, b_e, xprojT, G4E, 512, 1);

    enc_persist<<<NBLK, 256, 65536>>>(Whh_e);

    // enc @ Wih_c[:, :512]^T + b_c -> g_eprojT
    gemm128<<<dim3(24, 128), 256>>>(nullptr, Wih_c, b_c, eprojT, G4C, 640, 0);

    dnc_persist<<<NBLK, 384, (WC_F + HS_F + MEM_F) * 4>>>(Whh_c, Wih_c, out);
}

// round 8
// speedup vs baseline: 1.6254x; 1.0313x over previous
#include <cuda_runtime.h>
#include <math.h>

#define Hh   512
#define Rr   4
#define Ww   32
#define Nn   64
#define Bb   64
#define Tt   256
#define HIDC 759
#define KCOMB 896          // 759 h + 128 rv + 9 pad
#define G4C  3036
#define G4E  2048
#define EPSf 1e-6f

#define NBLK 128

typedef unsigned long long ull;

// ---- global buffers ----
__device__ float g_hTe [2][Hh*Bb];                    // encoder h, transposed [k][b]
__device__ float g_comb[2][KCOMB*Bb];                 // DNC [h(759) | rv(128) | pad] x [b]
__device__ float g_xprojT[(size_t)Tt*G4E*Bb];         // [t][col][b]
__device__ float g_eprojT[(size_t)Tt*G4C*Bb];         // [t][col][b]
__device__ float g_encT  [(size_t)Tt*Hh*Bb];          // [t][j][b]

__device__ unsigned g_cnt = 0u, g_gen = 0u;

__device__ __forceinline__ float sigm(float x)  { return 1.f/(1.f+expf(-x)); }
__device__ __forceinline__ float splus(float x) { return x > 0.f ? x + log1pf(expf(-x)) : log1pf(expf(x)); }

__device__ __forceinline__ ull pack2(float lo, float hi) {
    ull r;
    asm("mov.b64 %0, {%1, %2};" : "=l"(r) : "r"(__float_as_uint(lo)), "r"(__float_as_uint(hi)));
    return r;
}
__device__ __forceinline__ void fma2(ull& acc, ull a, ull b) {
    asm("fma.rn.f32x2 %0, %1, %2, %3;" : "=l"(acc) : "l"(a), "l"(b), "l"(acc));
}
__device__ __forceinline__ ull add2(ull a, ull b) {
    ull r; asm("add.rn.f32x2 %0, %1, %2;" : "=l"(r) : "l"(a), "l"(b)); return r;
}
__device__ __forceinline__ float lo2(ull v) {
    unsigned x, y; asm("mov.b64 {%0, %1}, %2;" : "=r"(x), "=r"(y) : "l"(v));
    return __uint_as_float(x);
}
__device__ __forceinline__ float hi2(ull v) {
    unsigned x, y; asm("mov.b64 {%0, %1}, %2;" : "=r"(x), "=r"(y) : "l"(v));
    return __uint_as_float(y);
}

__device__ __forceinline__ void grid_sync() {
    __threadfence();
    __syncthreads();
    if (threadIdx.x == 0) {
        volatile unsigned* vgen = &g_gen;
        unsigned g = *vgen;
        if (atomicAdd(&g_cnt, 1u) == (unsigned)(NBLK - 1)) {
            *((volatile unsigned*)&g_cnt) = 0u;
            __threadfence();
            *vgen = g + 1u;
        } else {
            while (*vgen == g) { __nanosleep(64); }
        }
    }
    __syncthreads();
}

__global__ void zero_bufs() {
    int n1 = 2*Hh*Bb, n2 = 2*KCOMB*Bb;
    for (int i = blockIdx.x*blockDim.x + threadIdx.x; i < n1; i += gridDim.x*blockDim.x)
        ((float*)g_hTe)[i] = 0.f;
    for (int i = blockIdx.x*blockDim.x + threadIdx.x; i < n2; i += gridDim.x*blockDim.x)
        ((float*)g_comb)[i] = 0.f;
}

// ============ big GEMM (f32x2):  proj[t][col][b] = bias[col] + sum_k A[(t,b)][k]*W[col][k] ============
__global__ void gemm128(const float* __restrict__ x, const float* __restrict__ Wm,
                        const float* __restrict__ bias, float* __restrict__ proj,
                        int Ncols, int ldw, int xmode) {
    __shared__ __align__(16) float As[16][132];
    __shared__ __align__(16) float Bs[16][132];
    int tid = threadIdx.x;
    int tx = tid & 15, ty = tid >> 4;
    int row0 = blockIdx.y * 128, col0 = blockIdx.x * 128;
    int ar = tid >> 2, ac = (tid & 3) * 4;

    long aoff0 = 0, aoff1 = 0;
    if (xmode) {
        int r0 = row0 + ar, r1 = r0 + 64;
        aoff0 = ((long)(r0 & 63) * Tt + (r0 >> 6)) * Hh;
        aoff1 = ((long)(r1 & 63) * Tt + (r1 >> 6)) * Hh;
    }
    int brow0 = col0 + ar, brow1 = brow0 + 64;
    bool bv0 = brow0 < Ncols, bv1 = brow1 < Ncols;
    const float* Bp0 = Wm + (long)brow0 * ldw;
    const float* Bp1 = Wm + (long)brow1 * ldw;

    ull acc2[8][4];
#pragma unroll
    for (int i = 0; i < 8; i++)
#pragma unroll
        for (int j = 0; j < 4; j++) acc2[i][j] = 0ULL;

    for (int k0 = 0; k0 < 512; k0 += 16) {
        float4 b0 = bv0 ? *(const float4*)(Bp0 + k0 + ac) : make_float4(0,0,0,0);
        float4 b1 = bv1 ? *(const float4*)(Bp1 + k0 + ac) : make_float4(0,0,0,0);
        if (xmode) {
            float4 a0 = *(const float4*)(x + aoff0 + k0 + ac);
            float4 a1 = *(const float4*)(x + aoff1 + k0 + ac);
            __syncthreads();
            As[ac+0][ar]=a0.x; As[ac+1][ar]=a0.y; As[ac+2][ar]=a0.z; As[ac+3][ar]=a0.w;
            As[ac+0][ar+64]=a1.x; As[ac+1][ar+64]=a1.y; As[ac+2][ar+64]=a1.z; As[ac+3][ar+64]=a1.w;
        } else {
            __syncthreads();
#pragma unroll
            for (int i = 0; i < 8; i++) {
                int e = i*256 + tid; int k = e >> 7, rr = e & 127;
                int r = row0 + rr;
                As[k][rr] = g_encT[(((size_t)(r >> 6))*Hh + k0 + k)*Bb + (r & 63)];
            }
        }
        Bs[ac+0][ar]=b0.x; Bs[ac+1][ar]=b0.y; Bs[ac+2][ar]=b0.z; Bs[ac+3][ar]=b0.w;
        Bs[ac+0][ar+64]=b1.x; Bs[ac+1][ar+64]=b1.y; Bs[ac+2][ar+64]=b1.z; Bs[ac+3][ar+64]=b1.w;
        __syncthreads();
#pragma unroll
        for (int k = 0; k < 16; k++) {
            float4 fa0 = *(const float4*)&As[k][ty*4];
            float4 fa1 = *(const float4*)&As[k][64 + ty*4];
            ulonglong2 bq0 = *(const ulonglong2*)&Bs[k][tx*4];
            ulonglong2 bq1 = *(const ulonglong2*)&Bs[k][64 + tx*4];
            ull bq[4] = {bq0.x, bq0.y, bq1.x, bq1.y};
            float af[8] = {fa0.x,fa0.y,fa0.z,fa0.w,fa1.x,fa1.y,fa1.z,fa1.w};
#pragma unroll
            for (int i = 0; i < 8; i++) {
                ull ap = pack2(af[i], af[i]);
#pragma unroll
                for (int j = 0; j < 4; j++) fma2(acc2[i][j], ap, bq[j]);
            }
        }
    }
#pragma unroll
    for (int i = 0; i < 8; i++) {
        int r = row0 + (i < 4 ? ty*4 + i : 64 + ty*4 + i - 4);
        int t = r >> 6, b = r & 63;
#pragma unroll
        for (int jj = 0; jj < 8; jj++) {
            int cix = col0 + (jj < 4 ? tx*4 + jj : 64 + tx*4 + jj - 4);
            if (cix < Ncols) {
                ull v = acc2[i][jj >> 1];
                float f = (jj & 1) ? hi2(v) : lo2(v);
                proj[((size_t)t*Ncols + cix)*Bb + b] = f + bias[cix];
            }
        }
    }
}

// ============ persistent encoder: 128 blocks x 256 threads (2jp x 2bh x 2ks x 32) ============
__global__ void __launch_bounds__(256, 1) enc_persist(const float* __restrict__ Whh) {
    extern __shared__ __align__(16) float sm[];
    float* Wc = sm;              // [jp2][g][k][jo] = 2*4*512*2 = 8192 floats
    float* Hs = sm + 8192;       // 128*64

    int tid = threadIdx.x, bid = blockIdx.x;
    int jb = bid * 4;
    int warp = tid >> 5, lane = tid & 31;
    int jp = warp >> 2;          // 0..1
    int sub = warp & 3;
    int bh = sub & 1, ks = sub >> 1;
    int b = bh*32 + lane;

    // cache weights interleaved over j-pairs
    for (int i = 0; i < 32; i++) {
        int idx = i*256 + tid;                 // 0..8191
        int jo = idx & 1, k = (idx >> 1) & 511, g = (idx >> 10) & 3, jpw = idx >> 12;
        int j = jb + jpw*2 + jo;
        Wc[idx] = Whh[((size_t)(g*Hh + j))*Hh + k];
    }
    float c0 = 0.f, c1 = 0.f;
    const float* wbase = Wc + jp*4096;

    for (int t = 0; t < Tt; t++) {
        int par = t & 1;
        const float* hin = g_hTe[par];
        ull a0 = 0ULL, a1 = 0ULL, a2 = 0ULL, a3 = 0ULL;
        for (int k0 = 0; k0 < 512; k0 += 128) {
            __syncthreads();
            const float4* src = (const float4*)(hin + (size_t)k0*Bb);
#pragma unroll
            for (int i = 0; i < 8; i++) {
                int q = i*256 + tid;
                ((float4*)Hs)[q] = __ldcg(src + q);
            }
            __syncthreads();
            int ke = ks*64 + 64;
#pragma unroll 4
            for (int kk = ks*64; kk < ke; kk += 2) {
                int kg = k0 + kk;
                ulonglong2 w0 = *(const ulonglong2*)(wbase + 0*1024 + kg*2);
                ulonglong2 w1 = *(const ulonglong2*)(wbase + 1*1024 + kg*2);
                ulonglong2 w2 = *(const ulonglong2*)(wbase + 2*1024 + kg*2);
                ulonglong2 w3 = *(const ulonglong2*)(wbase + 3*1024 + kg*2);
                float h0 = Hs[(kk+0)*64 + b], h1 = Hs[(kk+1)*64 + b];
                ull p0 = pack2(h0, h0), p1 = pack2(h1, h1);
                fma2(a0, w0.x, p0); fma2(a1, w1.x, p0); fma2(a2, w2.x, p0); fma2(a3, w3.x, p0);
                fma2(a0, w0.y, p1); fma2(a1, w1.y, p1); fma2(a2, w2.y, p1); fma2(a3, w3.y, p1);
            }
        }
        // ksplit reduce through SMEM
        __syncthreads();
        ull* red = (ull*)Hs;
        int slot = ((jp*2 + bh)*32 + lane)*4;
        if (ks == 1) { red[slot]=a0; red[slot+1]=a1; red[slot+2]=a2; red[slot+3]=a3; }
        __syncthreads();
        if (ks == 0) {
            a0 = add2(a0, red[slot]); a1 = add2(a1, red[slot+1]);
            a2 = add2(a2, red[slot+2]); a3 = add2(a3, red[slot+3]);
            const float* xp = g_xprojT + (size_t)t*G4E*Bb;
            int j0 = jb + jp*2, j1 = j0 + 1;
            float gi0 = xp[(0*Hh + j0)*Bb + b] + lo2(a0);
            float gf0 = xp[(1*Hh + j0)*Bb + b] + lo2(a1);
            float gg0 = xp[(2*Hh + j0)*Bb + b] + lo2(a2);
            float go0 = xp[(3*Hh + j0)*Bb + b] + lo2(a3);
            float gi1 = xp[(0*Hh + j1)*Bb + b] + hi2(a0);
            float gf1 = xp[(1*Hh + j1)*Bb + b] + hi2(a1);
            float gg1 = xp[(2*Hh + j1)*Bb + b] + hi2(a2);
            float go1 = xp[(3*Hh + j1)*Bb + b] + hi2(a3);
            c0 = sigm(gf0)*c0 + sigm(gi0)*tanhf(gg0);
            c1 = sigm(gf1)*c1 + sigm(gi1)*tanhf(gg1);
            float hn0 = sigm(go0)*tanhf(c0);
            float hn1 = sigm(go1)*tanhf(c1);
            g_hTe[par^1][j0*Bb + b] = hn0;
            g_hTe[par^1][j1*Bb + b] = hn1;
            g_encT[((size_t)t*Hh + j0)*Bb + b] = hn0;
            g_encT[((size_t)t*Hh + j1)*Bb + b] = hn1;
        }
        grid_sync();
    }
}

// ============ persistent DNC: 128 blocks x 384 threads (3jp x 2bh x 2ks x 32) ============
#define WC_F   (24*KCOMB)           // 21504
#define HS_F   (128*64)             // 8192
#define MEM_F  8512

__global__ void __launch_bounds__(384, 1) dnc_persist(const float* __restrict__ Whh_c,
                                                      const float* __restrict__ Wih_c,
                                                      float* __restrict__ out) {
    extern __shared__ __align__(16) float sm[];
    float* Wc  = sm;
    float* Hs  = sm + WC_F;
    float* MEM = sm + WC_F + HS_F;

    float* Ms   = MEM;               // 64x33
    float* Ls   = MEM + 2112;        // 64x65
    float* u_s  = MEM + 6272;
    float* p_s  = u_s + 64;
    float* wwo  = p_s + 64;
    float* wwn  = wwo + 64;
    float* su   = wwn + 64;
    float* asrt = su + 64;
    float* cwv  = asrt + 64;
    float* simv = cwv + 64;
    float* mno  = simv + 64;
    int*   rnk  = (int*)(mno + 64);
    float* wro  = mno + 128;         // 4x64
    float* wrn  = wro + 256;
    float* crs  = wrn + 256;
    float* fws  = crs + 256;
    float* bws  = fws + 256;
    float* rk   = bws + 256;         // 4x32
    float* wk   = rk + 128;
    float* er   = wk + 32;
    float* wv   = er + 32;
    float* rs   = wv + 32;           // 4
    float* fg   = rs + 4;
    float* rmm  = fg + 4;            // 12
    float* rmraw= rmm + 12;          // 12
    float* scal = rmraw + 12;        // 11

    int tid = threadIdx.x, bid = blockIdx.x;
    int jb = bid * 6;
    int warp = tid >> 5, lane = tid & 31;
    int jp = warp >> 2;              // 0..2
    int sub = warp & 3;
    int bh = sub & 1, ks = sub >> 1;
    int b = bh*32 + lane;

    // cache weights [jp][g][k<896][jo]
    for (int i = 0; i < 56; i++) {
        int idx = i*384 + tid;       // exactly 21504
        int jo = idx & 1;
        int rest = idx >> 1;                  // jp*3584 + g*896 + k
        int k = rest % 896;
        int gg2 = rest / 896;
        int jpw = gg2 >> 2, g = gg2 & 3;
        int j = jb + jpw*2 + jo;
        float v = 0.f;
        if (j < HIDC) {
            if (k < HIDC)            v = Whh_c[((size_t)(g*HIDC + j))*HIDC + k];
            else if (k < HIDC + 128) v = Wih_c[((size_t)(g*HIDC + j))*640 + 512 + (k - HIDC)];
        }
        Wc[idx] = v;
    }
    if (bid < 64) {
        for (int idx = tid; idx < MEM_F; idx += 384) MEM[idx] = 0.f;
    }
    float c0 = 0.f, c1 = 0.f;
    const float* wbase = Wc + jp*7168;

    for (int t = 0; t < Tt; t++) {
        int par = t & 1;
        const float* combP = g_comb[par];
        float* combN = g_comb[par^1];

        ull a0 = 0ULL, a1 = 0ULL, a2 = 0ULL, a3 = 0ULL;
        for (int k0 = 0; k0 < KCOMB; k0 += 128) {
            __syncthreads();
            const float4* src = (const float4*)(combP + (size_t)k0*Bb);
#pragma unroll
            for (int i = 0; i < 6; i++) {
                int q = i*384 + tid;
                if (q < 2048) ((float4*)Hs)[q] = __ldcg(src + q);
            }
            __syncthreads();
            int ke = ks*64 + 64;
#pragma unroll 4
            for (int kk = ks*64; kk < ke; kk += 2) {
                int kg = k0 + kk;
                ulonglong2 w0 = *(const ulonglong2*)(wbase + 0*1792 + kg*2);
                ulonglong2 w1 = *(const ulonglong2*)(wbase + 1*1792 + kg*2);
                ulonglong2 w2 = *(const ulonglong2*)(wbase + 2*1792 + kg*2);
                ulonglong2 w3 = *(const ulonglong2*)(wbase + 3*1792 + kg*2);
                float h0 = Hs[(kk+0)*64 + b], h1 = Hs[(kk+1)*64 + b];
                ull p0 = pack2(h0, h0), p1 = pack2(h1, h1);
                fma2(a0, w0.x, p0); fma2(a1, w1.x, p0); fma2(a2, w2.x, p0); fma2(a3, w3.x, p0);
                fma2(a0, w0.y, p1); fma2(a1, w1.y, p1); fma2(a2, w2.y, p1); fma2(a3, w3.y, p1);
            }
        }
        // ksplit reduce
        __syncthreads();
        ull* red = (ull*)Hs;
        int slot = ((jp*2 + bh)*32 + lane)*4;
        if (ks == 1) { red[slot]=a0; red[slot+1]=a1; red[slot+2]=a2; red[slot+3]=a3; }
        __syncthreads();
        if (ks == 0) {
            a0 = add2(a0, red[slot]); a1 = add2(a1, red[slot+1]);
            a2 = add2(a2, red[slot+2]); a3 = add2(a3, red[slot+3]);
            const float* ep = g_eprojT + (size_t)t*G4C*Bb;
            int j0 = jb + jp*2;
#pragma unroll
            for (int jo = 0; jo < 2; jo++) {
                int j = j0 + jo;
                if (j < HIDC) {
                    float ai = jo ? hi2(a0) : lo2(a0);
                    float af = jo ? hi2(a1) : lo2(a1);
                    float ag = jo ? hi2(a2) : lo2(a2);
                    float ao = jo ? hi2(a3) : lo2(a3);
                    float gi = ep[((size_t)(0*HIDC + j))*Bb + b] + ai;
                    float gf = ep[((size_t)(1*HIDC + j))*Bb + b] + af;
                    float gg = ep[((size_t)(2*HIDC + j))*Bb + b] + ag;
                    float go = ep[((size_t)(3*HIDC + j))*Bb + b] + ao;
                    float& cc = jo ? c1 : c0;
                    cc = sigm(gf)*cc + sigm(gi)*tanhf(gg);
                    float hn = sigm(go)*tanhf(cc);
                    combN[j*Bb + b] = hn;
                    if (j < Hh) out[((size_t)b*Tt + t)*Hh + j] = hn;
                }
            }
        }
        grid_sync();

        // ---------------- memory machinery (blocks 0..63, batch = bid) ----------------
        if (bid < 64) {
            int mb = bid;
            if (tid < 247) {
                float v = __ldcg(&combN[(Hh + tid)*Bb + mb]);
                if      (tid < 128) rk[tid] = tanhf(v);
                else if (tid < 132) rs[tid-128] = splus(v);
                else if (tid < 164) wk[tid-132] = tanhf(v);
                else if (tid ==164) scal[0] = splus(v);
                else if (tid < 197) er[tid-165] = sigm(v);
                else if (tid < 229) wv[tid-197] = tanhf(v);
                else if (tid < 233) fg[tid-229] = sigm(v);
                else if (tid ==233) scal[1] = sigm(v);
                else if (tid ==234) scal[2] = sigm(v);
                else                rmraw[tid-235] = v;
            }
            __syncthreads();
            if (tid < 4) {
                float x0=rmraw[tid*3], x1=rmraw[tid*3+1], x2=rmraw[tid*3+2];
                float m = fmaxf(x0, fmaxf(x1, x2));
                float e0=expf(x0-m), e1=expf(x1-m), e2=expf(x2-m), s=e0+e1+e2;
                rmm[tid*3]=e0/s; rmm[tid*3+1]=e1/s; rmm[tid*3+2]=e2/s;
            } else if (tid == 4) {
                float s = EPSf;
                for (int w = 0; w < 32; w++) s += wk[w]*wk[w];
                scal[3] = rsqrtf(s);
            } else if (tid >= 8 && tid < 12) {
                int r = tid - 8; float s = EPSf;
                for (int w = 0; w < 32; w++) s += rk[r*32+w]*rk[r*32+w];
                scal[5+r] = rsqrtf(s);
            } else if (tid >= 64 && tid < 128) {
                int n = tid - 64;
                float psi = 1.f;
#pragma unroll
                for (int r = 0; r < 4; r++) psi *= 1.f - fg[r]*wro[r*64+n];
                float uo = u_s[n], w = wwo[n];
                u_s[n] = (uo + w - uo*w) * psi;
            }
            __syncthreads();
            if (tid < 64) {
                float un = u_s[tid]; int r = 0;
                for (int m = 0; m < 64; m++) {
                    float um = u_s[m];
                    r += (um < un) || (um == un && m < tid);
                }
                rnk[tid] = r;
                su[r] = un;
            } else if (tid < 128) {
                int n = tid - 64; float ss = EPSf, d = 0.f;
                for (int w = 0; w < 32; w++) { float m = Ms[n*33+w]; ss += m*m; d += wk[w]*m; }
                simv[n] = d * rsqrtf(ss) * scal[3];
            }
            __syncthreads();
            if (tid == 0) {
                float cp = 1.f;
                for (int i = 0; i < 64; i++) { asrt[i] = (1.f - su[i]) * cp; cp *= su[i]; }
                float mx = -1e30f;
                for (int n = 0; n < 64; n++) mx = fmaxf(mx, simv[n]*scal[0]);
                scal[9] = mx;
            }
            __syncthreads();
            if (tid < 64) cwv[tid] = expf(simv[tid]*scal[0] - scal[9]);
            __syncthreads();
            if (tid == 0) { float s = 0.f; for (int n = 0; n < 64; n++) s += cwv[n]; scal[10] = s; }
            __syncthreads();
            if (tid < 64) {
                float cc = cwv[tid] / scal[10];
                float a  = asrt[rnk[tid]];
                wwn[tid] = scal[2] * (scal[1]*a + (1.f-scal[1])*cc);
            }
            __syncthreads();
            if (tid == 0) { float s = 0.f; for (int n = 0; n < 64; n++) s += wwn[n]; scal[4] = s; }
            if (tid < 256) {
#pragma unroll
                for (int i = 0; i < 8; i++) {
                    int e = i*256 + tid, n = e>>5, w = e&31;
                    Ms[n*33+w] = Ms[n*33+w]*(1.f - wwn[n]*er[w]) + wwn[n]*wv[w];
                }
#pragma unroll
                for (int i = 0; i < 16; i++) {
                    int e = i*256 + tid, ii = e>>6, jj = e&63;
                    Ls[ii*65+jj] = (ii == jj) ? 0.f
                               : (1.f - wwn[ii] - wwn[jj])*Ls[ii*65+jj] + wwn[ii]*p_s[jj];
                }
            }
            __syncthreads();
            if (tid < 64) {
                p_s[tid] = (1.f - scal[4])*p_s[tid] + wwn[tid];
                float ss = EPSf;
                for (int w = 0; w < 32; w++) ss += Ms[tid*33+w]*Ms[tid*33+w];
                mno[tid] = rsqrtf(ss);
            }
            __syncthreads();
            if (tid < 256) {
                int r = tid >> 6, n = tid & 63;
                float d = 0.f;
                for (int w = 0; w < 32; w++) d += rk[r*32+w]*Ms[n*33+w];
                crs[r*64+n] = d * mno[n] * scal[5+r] * rs[r];
                float f = 0.f, bb2 = 0.f;
                for (int m = 0; m < 64; m++) {
                    float wrm = wro[r*64+m];
                    f   += Ls[n*65+m]*wrm;
                    bb2 += Ls[m*65+n]*wrm;
                }
                fws[r*64+n] = f; bws[r*64+n] = bb2;
            }
            __syncthreads();
            if (tid < 4) {
                int r = tid; float mx = -1e30f;
                for (int n = 0; n < 64; n++) mx = fmaxf(mx, crs[r*64+n]);
                float s = 0.f;
                for (int n = 0; n < 64; n++) { float e = expf(crs[r*64+n]-mx); crs[r*64+n] = e; s += e; }
                float inv = 1.f/s;
                for (int n = 0; n < 64; n++) crs[r*64+n] *= inv;
            }
            __syncthreads();
            if (tid < 256) {
                int r = tid >> 6, n = tid & 63;
                wrn[r*64+n] = rmm[r*3+0]*bws[r*64+n] + rmm[r*3+1]*crs[r*64+n] + rmm[r*3+2]*fws[r*64+n];
            }
            __syncthreads();
            if (tid < 128) {
                int r = tid >> 5, w = tid & 31;
                float s = 0.f;
                for (int n = 0; n < 64; n++) s += wrn[r*64+n]*Ms[n*33+w];
                combN[(HIDC + tid)*Bb + mb] = s;
            }
            if (tid < 64) wwo[tid] = wwn[tid];
            if (tid < 256) wro[tid] = wrn[tid];
            __syncthreads();
        }
        grid_sync();
    }
}

extern "C" void kernel_launch(void* const* d_in, const int* in_sizes, int n_in,
                              void* d_out, int out_size) {
    const float* x     = (const float*)d_in[0];
    const float* Wih_e = (const float*)d_in[1];
    const float* Whh_e = (const float*)d_in[2];
    const float* b_e   = (const float*)d_in[3];
    const float* Wih_c = (const float*)d_in[4];
    const float* Whh_c = (const float*)d_in[5];
    const float* b_c   = (const float*)d_in[6];
    float* out = (float*)d_out;

    static int attrs_set = 0;
    if (!attrs_set) {
        cudaFuncSetAttribute(enc_persist, cudaFuncAttributeMaxDynamicSharedMemorySize, 65536);
        cudaFuncSetAttribute(dnc_persist, cudaFuncAttributeMaxDynamicSharedMemorySize,
                             (WC_F + HS_F + MEM_F) * 4);
        attrs_set = 1;
    }

    float* xprojT; cudaGetSymbolAddress((void**)&xprojT, g_xprojT);
    float* eprojT; cudaGetSymbolAddress((void**)&eprojT, g_eprojT);

    zero_bufs<<<64, 256>>>();

    gemm128<<<dim3(16, 128), 256>>>(x, Wih_e, b_e, xprojT, G4E, 512, 1);

    enc_persist<<<NBLK, 256, 65536>>>(Whh_e);

    gemm128<<<dim3(24, 128), 256>>>(nullptr, Wih_c, b_c, eprojT, G4C, 640, 0);

    dnc_persist<<<NBLK, 384, (WC_F + HS_F + MEM_F) * 4>>>(Whh_c, Wih_c, out);
}